// round 14
// baseline (speedup 1.0000x reference)
#include <cuda_runtime.h>

// Problem constants (fixed by the reference):
//   N=4096 samples, D=128 input dim, P=128 pe dim (== D), H=256 hidden.
#define NN 4096
#define DD 128
#define HH 256

// Scratch: base[n][h] = (x @ W1[:D])[n][h] + b1[h]
__device__ float g_base[NN * HH];

typedef unsigned long long u64;

__device__ __forceinline__ u64 pk2(float x, float y) {
    u64 r; asm("mov.b64 %0, {%1, %2};" : "=l"(r) : "f"(x), "f"(y)); return r;
}
__device__ __forceinline__ u64 fma2_(u64 a, u64 b, u64 c) {
    u64 d; asm("fma.rn.f32x2 %0, %1, %2, %3;" : "=l"(d) : "l"(a), "l"(b), "l"(c)); return d;
}
__device__ __forceinline__ u64 add2_(u64 a, u64 b) {
    u64 d; asm("add.rn.f32x2 %0, %1, %2;" : "=l"(d) : "l"(a), "l"(b)); return d;
}
__device__ __forceinline__ u64 relu2_(u64 a) {
    float x, y;
    asm("mov.b64 {%0, %1}, %2;" : "=f"(x), "=f"(y) : "l"(a));
    x = fmaxf(x, 0.0f); y = fmaxf(y, 0.0f);
    return pk2(x, y);
}
__device__ __forceinline__ float2 unpk(u64 a) {
    float2 v; asm("mov.b64 {%0, %1}, %2;" : "=f"(v.x), "=f"(v.y) : "l"(a)); return v;
}

// ---------------------------------------------------------------------------
// K1: base = x @ W1[:D] + b1   (4096 x 256, K=128), f32x2 accumulators.
// ---------------------------------------------------------------------------
__global__ __launch_bounds__(256) void nimo_base_kernel(
    const float* __restrict__ x, const float* __restrict__ W1,
    const float* __restrict__ b1, float* __restrict__ out)
{
    __shared__ __align__(16) float xs[32][68];
    __shared__ __align__(16) float ws[32][68];

    const int tid = threadIdx.x;
    const int n0 = blockIdx.x * 64;
    const int h0 = blockIdx.y * 64;
    const int tx = tid & 15;
    const int ty = tid >> 4;

    u64 acc[4][2];
#pragma unroll
    for (int i = 0; i < 4; i++) { acc[i][0] = 0ull; acc[i][1] = 0ull; }

    for (int kt = 0; kt < DD; kt += 32) {
#pragma unroll
        for (int i = 0; i < 8; i++) {
            int e = tid + i * 256;
            int r = e >> 5, k = e & 31;
            xs[k][r] = x[(n0 + r) * DD + kt + k];
        }
#pragma unroll
        for (int i = 0; i < 8; i++) {
            int e = tid + i * 256;
            int k = e >> 6, c = e & 63;
            ws[k][c] = W1[(kt + k) * HH + h0 + c];
        }
        __syncthreads();
#pragma unroll
        for (int kk = 0; kk < 32; kk++) {
            float4 xv = *(const float4*)&xs[kk][ty * 4];
            ulonglong2 wv = *(const ulonglong2*)&ws[kk][tx * 4];
            u64 x0 = pk2(xv.x, xv.x), x1 = pk2(xv.y, xv.y);
            u64 x2 = pk2(xv.z, xv.z), x3 = pk2(xv.w, xv.w);
            acc[0][0] = fma2_(x0, wv.x, acc[0][0]); acc[0][1] = fma2_(x0, wv.y, acc[0][1]);
            acc[1][0] = fma2_(x1, wv.x, acc[1][0]); acc[1][1] = fma2_(x1, wv.y, acc[1][1]);
            acc[2][0] = fma2_(x2, wv.x, acc[2][0]); acc[2][1] = fma2_(x2, wv.y, acc[2][1]);
            acc[3][0] = fma2_(x3, wv.x, acc[3][0]); acc[3][1] = fma2_(x3, wv.y, acc[3][1]);
        }
        __syncthreads();
    }

    ulonglong2 bv = *(const ulonglong2*)&b1[h0 + tx * 4];
#pragma unroll
    for (int i = 0; i < 4; i++) {
        ulonglong2 o;
        o.x = add2_(acc[i][0], bv.x);
        o.y = add2_(acc[i][1], bv.y);
        *(ulonglong2*)&g_base[(n0 + ty * 4 + i) * HH + h0 + tx * 4] = o;
    }

    if (blockIdx.y == 0 && tid < 64) out[(n0 + tid) * (DD + 1)] = 1.0f;
}

// ---------------------------------------------------------------------------
// K2: per (n, j):
//   g = sum_h relu(base[n,h] + W1[D+j,h] - x[n,j]*W1[j,h]) * W2[h]
//   out[n, 1+j] = x[n,j] * (1 + b2 + g)
//
// Full 32-lane h-split (lane owns 8 h); warp owns 4 n (bp = 16 u64 -> ~85
// regs -> 6 CTAs/SM, ~24 warps resident). Per j: 2 double-buffered LDG.128
// (W1 row) + 2 LDG.128 (pe row), all coalesced & L1-hot; x read as one
// ld.shared.b64 of pre-negated pairs. Reduction: value-splitting tree
// (2+1 shfl) then 3-shfl butterfly within 8-lane groups; writer lanes
// (lane&7)==0, n index = lane>>3.
// Block = 128 thr (4 warps, 16 n); grid = (256 n-tiles) x (4 j-tiles).
// ---------------------------------------------------------------------------
__global__ __launch_bounds__(128, 6) void nimo_main_kernel(
    const float* __restrict__ x, const float* __restrict__ W1,
    const float* __restrict__ W2, const float* __restrict__ b2,
    float* __restrict__ out)
{
    __shared__ __align__(8) float2 xs2[16][33];   // (-x, -x) per (n', j')

    const int tid  = threadIdx.x;
    const int lane = tid & 31;
    const int warp = tid >> 5;
    const int n0   = blockIdx.x * 16;
    const int j0   = blockIdx.y * 32;
    const int nb   = n0 + warp * 4;

    // ---- stage x tile as negated duplicated pairs (16 n x 32 j) ----
#pragma unroll
    for (int i = 0; i < 4; i++) {
        int e = tid + i * 128;
        int r = e >> 5, c = e & 31;
        float v = x[(n0 + r) * DD + j0 + c];
        xs2[r][c] = make_float2(-v, -v);
    }

    // ---- persistent registers (direct packed loads) ----
    u64 bp[4][4], w2p[4];
    {
        const ulonglong2* w2r = (const ulonglong2*)W2;
        ulonglong2 wa = w2r[lane], wb = w2r[32 + lane];
        w2p[0] = wa.x; w2p[1] = wa.y; w2p[2] = wb.x; w2p[3] = wb.y;
#pragma unroll
        for (int i = 0; i < 4; i++) {
            const ulonglong2* br = (const ulonglong2*)&g_base[(nb + i) * HH];
            ulonglong2 ba = br[lane], bb = br[32 + lane];
            bp[i][0] = ba.x; bp[i][1] = ba.y; bp[i][2] = bb.x; bp[i][3] = bb.y;
        }
    }
    const float ob2 = 1.0f + b2[0];
    const bool h16 = (lane & 16) != 0;
    const bool h8  = (lane & 8) != 0;

    __syncthreads();

    // ---- double-buffered W1 row (packed) ----
    ulonglong2 fwa, fwb;
    {
        const ulonglong2* w1r = (const ulonglong2*)&W1[j0 * HH];
        fwa = w1r[lane]; fwb = w1r[32 + lane];
    }

#pragma unroll 1
    for (int jj = 0; jj < 32; jj++) {
        const int j = j0 + jj;
        const ulonglong2* per = (const ulonglong2*)&W1[(DD + j) * HH];
        ulonglong2 pa = per[lane], pb = per[32 + lane];
        u64 w1p0 = fwa.x, w1p1 = fwa.y, w1p2 = fwb.x, w1p3 = fwb.y;
        if (jj < 31) {
            const ulonglong2* nw = (const ulonglong2*)&W1[(j + 1) * HH];
            fwa = nw[lane]; fwb = nw[32 + lane];
        }
        u64 pep0 = pa.x, pep1 = pa.y, pep2 = pb.x, pep3 = pb.y;

        float s[4];
#pragma unroll
        for (int i = 0; i < 4; i++) {
            const u64 nx2 = *(const u64*)&xs2[warp * 4 + i][jj];  // (-xj,-xj)
            u64 a0, a1;
            a0 = fma2_(relu2_(add2_(fma2_(nx2, w1p0, pep0), bp[i][0])), w2p[0], 0ull);
            a1 = fma2_(relu2_(add2_(fma2_(nx2, w1p1, pep1), bp[i][1])), w2p[1], 0ull);
            a0 = fma2_(relu2_(add2_(fma2_(nx2, w1p2, pep2), bp[i][2])), w2p[2], a0);
            a1 = fma2_(relu2_(add2_(fma2_(nx2, w1p3, pep3), bp[i][3])), w2p[3], a1);
            float2 t = unpk(add2_(a0, a1));
            s[i] = t.x + t.y;
        }

        // ---- value-splitting shuffle reduction: 4 vals -> 1 per lane ----
        // level 1 (xor 16): keep 2, send 2. low lanes keep n {0,1}.
#pragma unroll
        for (int k = 0; k < 2; k++) {
            float snd = h16 ? s[k] : s[k + 2];
            float kp  = h16 ? s[k + 2] : s[k];
            s[k] = kp + __shfl_xor_sync(0xffffffffu, snd, 16);
        }
        // level 2 (xor 8): keep 1, send 1. bit8 lanes keep odd n.
        {
            float snd = h8 ? s[0] : s[1];
            float kp  = h8 ? s[1] : s[0];
            s[0] = kp + __shfl_xor_sync(0xffffffffu, snd, 8);
        }
        // butterfly within 8-lane group
        s[0] += __shfl_xor_sync(0xffffffffu, s[0], 4);
        s[0] += __shfl_xor_sync(0xffffffffu, s[0], 2);
        s[0] += __shfl_xor_sync(0xffffffffu, s[0], 1);

        // group g = lane>>3 holds the full sum for n = nb + g
        if ((lane & 7) == 0) {
            const int v = lane >> 3;
            const float nxj = xs2[warp * 4 + v][jj].x;   // = -xj
            out[(nb + v) * (DD + 1) + 1 + j] = -(nxj * (ob2 + s[0]));
        }
    }
}

extern "C" void kernel_launch(void* const* d_in, const int* in_sizes, int n_in,
                              void* d_out, int out_size)
{
    const float* x  = (const float*)d_in[0];
    const float* W1 = (const float*)d_in[1];
    const float* b1 = (const float*)d_in[2];
    const float* W2 = (const float*)d_in[3];
    const float* b2 = (const float*)d_in[4];
    float* out = (float*)d_out;

    nimo_base_kernel<<<dim3(64, 4), 256>>>(x, W1, b1, out);
    // K2: 256 n-tiles of 16 x 4 j-tiles of 32.
    nimo_main_kernel<<<dim3(256, 4), 128>>>(x, W1, W2, b2, out);
}

// round 16
// speedup vs baseline: 1.1389x; 1.1389x over previous
#include <cuda_runtime.h>

// Problem constants (fixed by the reference):
//   N=4096 samples, D=128 input dim, P=128 pe dim (== D), H=256 hidden.
#define NN 4096
#define DD 128
#define HH 256
#define JT 16   // j-tile per block in K2

// Scratch: base[n][h] = (x @ W1[:D])[n][h] + b1[h]
__device__ float g_base[NN * HH];

typedef unsigned long long u64;

__device__ __forceinline__ u64 pk2(float x, float y) {
    u64 r; asm("mov.b64 %0, {%1, %2};" : "=l"(r) : "f"(x), "f"(y)); return r;
}
__device__ __forceinline__ u64 fma2_(u64 a, u64 b, u64 c) {
    u64 d; asm("fma.rn.f32x2 %0, %1, %2, %3;" : "=l"(d) : "l"(a), "l"(b), "l"(c)); return d;
}
__device__ __forceinline__ u64 add2_(u64 a, u64 b) {
    u64 d; asm("add.rn.f32x2 %0, %1, %2;" : "=l"(d) : "l"(a), "l"(b)); return d;
}
__device__ __forceinline__ u64 relu2_(u64 a) {
    float x, y;
    asm("mov.b64 {%0, %1}, %2;" : "=f"(x), "=f"(y) : "l"(a));
    x = fmaxf(x, 0.0f); y = fmaxf(y, 0.0f);
    return pk2(x, y);
}
__device__ __forceinline__ float2 unpk(u64 a) {
    float2 v; asm("mov.b64 {%0, %1}, %2;" : "=f"(v.x), "=f"(v.y) : "l"(a)); return v;
}

// ---------------------------------------------------------------------------
// K1: base = x @ W1[:D] + b1   (4096 x 256, K=128), f32x2 accumulators.
// Tiles: 32(n) x 64(h) x 32(k); 256 threads; microtile 2n x 4h.
// Grid (128, 4) = 512 blocks (~3.5 CTAs/SM) to cover the sync latency.
// Also writes the leading ones column of the output (blockIdx.y == 0).
// ---------------------------------------------------------------------------
__global__ __launch_bounds__(256) void nimo_base_kernel(
    const float* __restrict__ x, const float* __restrict__ W1,
    const float* __restrict__ b1, float* __restrict__ out)
{
    __shared__ __align__(16) float xs[32][34];  // [k][n] transposed, padded (even stride)
    __shared__ __align__(16) float ws[32][68];  // [k][h], padded

    const int tid = threadIdx.x;
    const int n0 = blockIdx.x * 32;
    const int h0 = blockIdx.y * 64;
    const int tx = tid & 15;   // h group -> 4 h (2 packed pairs)
    const int ty = tid >> 4;   // n group -> 2 n

    u64 acc[2][2];
    acc[0][0] = acc[0][1] = acc[1][0] = acc[1][1] = 0ull;

    for (int kt = 0; kt < DD; kt += 32) {
#pragma unroll
        for (int i = 0; i < 4; i++) {           // 32n x 32k = 1024
            int e = tid + i * 256;
            int r = e >> 5, k = e & 31;
            xs[k][r] = x[(n0 + r) * DD + kt + k];
        }
#pragma unroll
        for (int i = 0; i < 8; i++) {           // 32k x 64h = 2048
            int e = tid + i * 256;
            int k = e >> 6, c = e & 63;
            ws[k][c] = W1[(kt + k) * HH + h0 + c];
        }
        __syncthreads();
#pragma unroll
        for (int kk = 0; kk < 32; kk++) {
            float2 xv = *(const float2*)&xs[kk][ty * 2];
            ulonglong2 wv = *(const ulonglong2*)&ws[kk][tx * 4];
            u64 x0 = pk2(xv.x, xv.x), x1 = pk2(xv.y, xv.y);
            acc[0][0] = fma2_(x0, wv.x, acc[0][0]); acc[0][1] = fma2_(x0, wv.y, acc[0][1]);
            acc[1][0] = fma2_(x1, wv.x, acc[1][0]); acc[1][1] = fma2_(x1, wv.y, acc[1][1]);
        }
        __syncthreads();
    }

    ulonglong2 bv = *(const ulonglong2*)&b1[h0 + tx * 4];
#pragma unroll
    for (int i = 0; i < 2; i++) {
        ulonglong2 o;
        o.x = add2_(acc[i][0], bv.x);
        o.y = add2_(acc[i][1], bv.y);
        *(ulonglong2*)&g_base[(n0 + ty * 2 + i) * HH + h0 + tx * 4] = o;
    }

    if (blockIdx.y == 0 && tid < 32) out[(n0 + tid) * (DD + 1)] = 1.0f;
}

// ---------------------------------------------------------------------------
// K2: per (n, j):
//   g = sum_h relu(base[n,h] + W1[D+j,h] - x[n,j]*W1[j,h]) * W2[h]
//   out[n, 1+j] = x[n,j] * (1 + b2 + g)
//
// R7 layout: full 32-lane h-split (lane owns 8 h), warp owns 8 n; base[8nx8h]
// + W2[8h] register-persistent via DIRECT ulonglong2 packed loads (a float
// pair in memory IS an f32x2 operand -- no pack movs); W1 row double-buffered
// across j. Reduction: value-splitting shuffle tree (xor16 x4, xor8 x2,
// xor4 x1, butterfly xor2+xor1); lane 4v ends with the sum for n = nb + v.
// Block = 128 thr (4 warps, 32 n); grid = (128 n-tiles) x (8 j-tiles of 16)
// -> 1024 blocks, ~17% wave imbalance at 4 CTAs/SM (vs 33% at 512 blocks).
// ---------------------------------------------------------------------------
__global__ __launch_bounds__(128, 4) void nimo_main_kernel(
    const float* __restrict__ x, const float* __restrict__ W1,
    const float* __restrict__ W2, const float* __restrict__ b2,
    float* __restrict__ out)
{
    __shared__ __align__(8) float2 xs2[32][JT + 1];   // (-x, -x) per (n', j')

    const int tid  = threadIdx.x;
    const int lane = tid & 31;
    const int warp = tid >> 5;
    const int n0   = blockIdx.x * 32;
    const int j0   = blockIdx.y * JT;
    const int nb   = n0 + warp * 8;

    // ---- stage x tile as negated duplicated pairs (32 n x 16 j) ----
#pragma unroll
    for (int i = 0; i < 4; i++) {
        int e = tid + i * 128;
        int r = e >> 4, c = e & 15;
        float v = x[(n0 + r) * DD + j0 + c];
        xs2[r][c] = make_float2(-v, -v);
    }

    // ---- persistent registers (direct packed loads, no pk2) ----
    u64 bp[8][4], w2p[4];
    {
        const ulonglong2* w2r = (const ulonglong2*)W2;
        ulonglong2 wa = w2r[lane], wb = w2r[32 + lane];
        w2p[0] = wa.x; w2p[1] = wa.y; w2p[2] = wb.x; w2p[3] = wb.y;
#pragma unroll
        for (int i = 0; i < 8; i++) {
            const ulonglong2* br = (const ulonglong2*)&g_base[(nb + i) * HH];
            ulonglong2 ba = br[lane], bb = br[32 + lane];
            bp[i][0] = ba.x; bp[i][1] = ba.y; bp[i][2] = bb.x; bp[i][3] = bb.y;
        }
    }
    const float ob2 = 1.0f + b2[0];
    const bool h16 = (lane & 16) != 0;
    const bool h8  = (lane & 8) != 0;
    const bool h4  = (lane & 4) != 0;

    __syncthreads();

    // ---- double-buffered W1 row (packed) ----
    ulonglong2 fwa, fwb;
    {
        const ulonglong2* w1r = (const ulonglong2*)&W1[j0 * HH];
        fwa = w1r[lane]; fwb = w1r[32 + lane];
    }

#pragma unroll 1
    for (int jj = 0; jj < JT; jj++) {
        const int j = j0 + jj;
        const ulonglong2* per = (const ulonglong2*)&W1[(DD + j) * HH];
        ulonglong2 pa = per[lane], pb = per[32 + lane];
        u64 w1p0 = fwa.x, w1p1 = fwa.y, w1p2 = fwb.x, w1p3 = fwb.y;
        if (jj < JT - 1) {   // prefetch next W1 row (overlaps the math below)
            const ulonglong2* nw = (const ulonglong2*)&W1[(j + 1) * HH];
            fwa = nw[lane]; fwb = nw[32 + lane];
        }
        u64 pep0 = pa.x, pep1 = pa.y, pep2 = pb.x, pep3 = pb.y;

        float s[8];
#pragma unroll
        for (int i = 0; i < 8; i++) {
            const u64 nx2 = *(const u64*)&xs2[warp * 8 + i][jj];  // (-xj,-xj)
            u64 a0, a1;
            a0 = fma2_(relu2_(add2_(fma2_(nx2, w1p0, pep0), bp[i][0])), w2p[0], 0ull);
            a1 = fma2_(relu2_(add2_(fma2_(nx2, w1p1, pep1), bp[i][1])), w2p[1], 0ull);
            a0 = fma2_(relu2_(add2_(fma2_(nx2, w1p2, pep2), bp[i][2])), w2p[2], a0);
            a1 = fma2_(relu2_(add2_(fma2_(nx2, w1p3, pep3), bp[i][3])), w2p[3], a1);
            float2 t = unpk(add2_(a0, a1));
            s[i] = t.x + t.y;
        }

        // ---- value-splitting shuffle reduction: 8 vals -> 1 per lane ----
#pragma unroll
        for (int k = 0; k < 4; k++) {
            float snd = h16 ? s[k] : s[k + 4];
            float kp  = h16 ? s[k + 4] : s[k];
            s[k] = kp + __shfl_xor_sync(0xffffffffu, snd, 16);
        }
#pragma unroll
        for (int k = 0; k < 2; k++) {
            float snd = h8 ? s[k] : s[k + 2];
            float kp  = h8 ? s[k + 2] : s[k];
            s[k] = kp + __shfl_xor_sync(0xffffffffu, snd, 8);
        }
        {
            float snd = h4 ? s[0] : s[1];
            float kp  = h4 ? s[1] : s[0];
            s[0] = kp + __shfl_xor_sync(0xffffffffu, snd, 4);
        }
        s[0] += __shfl_xor_sync(0xffffffffu, s[0], 2);
        s[0] += __shfl_xor_sync(0xffffffffu, s[0], 1);

        // lane 4v holds the full sum for n = nb + v
        if ((lane & 3) == 0) {
            const int v = lane >> 2;
            const float nxj = xs2[warp * 8 + v][jj].x;   // = -xj
            out[(nb + v) * (DD + 1) + 1 + j] = -(nxj * (ob2 + s[0]));
        }
    }
}

extern "C" void kernel_launch(void* const* d_in, const int* in_sizes, int n_in,
                              void* d_out, int out_size)
{
    const float* x  = (const float*)d_in[0];
    const float* W1 = (const float*)d_in[1];
    const float* b1 = (const float*)d_in[2];
    const float* W2 = (const float*)d_in[3];
    const float* b2 = (const float*)d_in[4];
    float* out = (float*)d_out;

    // K1: base GEMM + ones column. grid: 128 n-tiles x 4 h-tiles.
    nimo_base_kernel<<<dim3(128, 4), 256>>>(x, W1, b1, out);
    // K2: masked-MLP evaluation. grid: 128 n-tiles x 8 j-tiles of 16.
    nimo_main_kernel<<<dim3(128, 8), 128>>>(x, W1, W2, b2, out);
}

// round 17
// speedup vs baseline: 1.2970x; 1.1388x over previous
#include <cuda_runtime.h>

// Problem constants (fixed by the reference):
//   N=4096 samples, D=128 input dim, P=128 pe dim (== D), H=256 hidden.
#define NN 4096
#define DD 128
#define HH 256
#define JT 16   // j-tile per block in K2

// Scratch: base[n][h] = (x @ W1[:D])[n][h] + b1[h]
__device__ float g_base[NN * HH];

typedef unsigned long long u64;

__device__ __forceinline__ u64 pk2(float x, float y) {
    u64 r; asm("mov.b64 %0, {%1, %2};" : "=l"(r) : "f"(x), "f"(y)); return r;
}
__device__ __forceinline__ u64 fma2_(u64 a, u64 b, u64 c) {
    u64 d; asm("fma.rn.f32x2 %0, %1, %2, %3;" : "=l"(d) : "l"(a), "l"(b), "l"(c)); return d;
}
__device__ __forceinline__ u64 add2_(u64 a, u64 b) {
    u64 d; asm("add.rn.f32x2 %0, %1, %2;" : "=l"(d) : "l"(a), "l"(b)); return d;
}
__device__ __forceinline__ u64 relu2_(u64 a) {
    float x, y;
    asm("mov.b64 {%0, %1}, %2;" : "=f"(x), "=f"(y) : "l"(a));
    x = fmaxf(x, 0.0f); y = fmaxf(y, 0.0f);
    return pk2(x, y);
}
__device__ __forceinline__ float2 unpk(u64 a) {
    float2 v; asm("mov.b64 {%0, %1}, %2;" : "=f"(v.x), "=f"(v.y) : "l"(a)); return v;
}

// ---------------------------------------------------------------------------
// K1: base = x @ W1[:D] + b1   (4096 x 256, K=128), f32x2 accumulators.
// Proven 64(n) x 64(h) x 32(k) tiling; 256 threads; microtile 4n x 4h.
// Also writes the leading ones column of the output (blockIdx.y == 0).
// ---------------------------------------------------------------------------
__global__ __launch_bounds__(256) void nimo_base_kernel(
    const float* __restrict__ x, const float* __restrict__ W1,
    const float* __restrict__ b1, float* __restrict__ out)
{
    __shared__ __align__(16) float xs[32][68];
    __shared__ __align__(16) float ws[32][68];

    const int tid = threadIdx.x;
    const int n0 = blockIdx.x * 64;
    const int h0 = blockIdx.y * 64;
    const int tx = tid & 15;
    const int ty = tid >> 4;

    u64 acc[4][2];
#pragma unroll
    for (int i = 0; i < 4; i++) { acc[i][0] = 0ull; acc[i][1] = 0ull; }

    for (int kt = 0; kt < DD; kt += 32) {
#pragma unroll
        for (int i = 0; i < 8; i++) {
            int e = tid + i * 256;
            int r = e >> 5, k = e & 31;
            xs[k][r] = x[(n0 + r) * DD + kt + k];
        }
#pragma unroll
        for (int i = 0; i < 8; i++) {
            int e = tid + i * 256;
            int k = e >> 6, c = e & 63;
            ws[k][c] = W1[(kt + k) * HH + h0 + c];
        }
        __syncthreads();
#pragma unroll
        for (int kk = 0; kk < 32; kk++) {
            float4 xv = *(const float4*)&xs[kk][ty * 4];
            ulonglong2 wv = *(const ulonglong2*)&ws[kk][tx * 4];
            u64 x0 = pk2(xv.x, xv.x), x1 = pk2(xv.y, xv.y);
            u64 x2 = pk2(xv.z, xv.z), x3 = pk2(xv.w, xv.w);
            acc[0][0] = fma2_(x0, wv.x, acc[0][0]); acc[0][1] = fma2_(x0, wv.y, acc[0][1]);
            acc[1][0] = fma2_(x1, wv.x, acc[1][0]); acc[1][1] = fma2_(x1, wv.y, acc[1][1]);
            acc[2][0] = fma2_(x2, wv.x, acc[2][0]); acc[2][1] = fma2_(x2, wv.y, acc[2][1]);
            acc[3][0] = fma2_(x3, wv.x, acc[3][0]); acc[3][1] = fma2_(x3, wv.y, acc[3][1]);
        }
        __syncthreads();
    }

    ulonglong2 bv = *(const ulonglong2*)&b1[h0 + tx * 4];
#pragma unroll
    for (int i = 0; i < 4; i++) {
        ulonglong2 o;
        o.x = add2_(acc[i][0], bv.x);
        o.y = add2_(acc[i][1], bv.y);
        *(ulonglong2*)&g_base[(n0 + ty * 4 + i) * HH + h0 + tx * 4] = o;
    }

    if (blockIdx.y == 0 && tid < 64) out[(n0 + tid) * (DD + 1)] = 1.0f;
}

// ---------------------------------------------------------------------------
// K2: per (n, j):
//   g = sum_h relu(base[n,h] + W1[D+j,h] - x[n,j]*W1[j,h]) * W2[h]
//   out[n, 1+j] = x[n,j] * (1 + b2 + g)
//
// Full 32-lane h-split (lane owns 8 h), warp owns 8 n; base[8n x 8h] + W2[8h]
// register-persistent via direct ulonglong2 packed loads. The block's JT=16
// W1 rows + 16 pe rows (32 KB) are STAGED IN SHARED MEMORY once per block:
// the j-loop's only memory ops are 4 conflict-free lane-indexed LDS.128
// (fixed 29-cyc latency; kills the L2-latency LDG stalls of the previous
// version, since W1 at 256 KB exceeds the 228 KB L1) plus 1 ld.shared.b64
// of pre-negated x per (i). Reduction: value-splitting shuffle tree.
// Block = 128 thr (4 warps, 32 n); grid = (128 n-tiles) x (8 j-tiles of 16).
// ---------------------------------------------------------------------------
__global__ __launch_bounds__(128, 4) void nimo_main_kernel(
    const float* __restrict__ x, const float* __restrict__ W1,
    const float* __restrict__ W2, const float* __restrict__ b2,
    float* __restrict__ out)
{
    __shared__ __align__(16) float wtile[2 * JT][HH];   // rows 0..15 = W1[j0+r], 16..31 = W1[DD+j0+r]
    __shared__ __align__(8) float2 xs2[32][JT + 1];     // (-x, -x) per (n', j')

    const int tid  = threadIdx.x;
    const int lane = tid & 31;
    const int warp = tid >> 5;
    const int n0   = blockIdx.x * 32;
    const int j0   = blockIdx.y * JT;
    const int nb   = n0 + warp * 8;

    // ---- stage W1 + pe rows (coalesced LDG.128 -> contiguous STS.128) ----
#pragma unroll
    for (int p = 0; p < 16; p++) {
        int e = tid + p * 128;           // float4 index: 2048 total
        int r = e >> 6;                  // row 0..31
        int c = e & 63;                  // float4 within row
        int src = (r < JT) ? (j0 + r) : (DD + j0 + (r - JT));
        float4 v = *(const float4*)&W1[src * HH + c * 4];
        *(float4*)&wtile[r][c * 4] = v;
    }

    // ---- stage x tile as negated duplicated pairs (32 n x 16 j) ----
#pragma unroll
    for (int i = 0; i < 4; i++) {
        int e = tid + i * 128;
        int r = e >> 4, c = e & 15;
        float v = x[(n0 + r) * DD + j0 + c];
        xs2[r][c] = make_float2(-v, -v);
    }

    // ---- persistent registers (direct packed loads) ----
    u64 bp[8][4], w2p[4];
    {
        const ulonglong2* w2r = (const ulonglong2*)W2;
        ulonglong2 wa = w2r[lane], wb = w2r[32 + lane];
        w2p[0] = wa.x; w2p[1] = wa.y; w2p[2] = wb.x; w2p[3] = wb.y;
#pragma unroll
        for (int i = 0; i < 8; i++) {
            const ulonglong2* br = (const ulonglong2*)&g_base[(nb + i) * HH];
            ulonglong2 ba = br[lane], bb = br[32 + lane];
            bp[i][0] = ba.x; bp[i][1] = ba.y; bp[i][2] = bb.x; bp[i][3] = bb.y;
        }
    }
    const float ob2 = 1.0f + b2[0];
    const bool h16 = (lane & 16) != 0;
    const bool h8  = (lane & 8) != 0;
    const bool h4  = (lane & 4) != 0;

    __syncthreads();

#pragma unroll 1
    for (int jj = 0; jj < JT; jj++) {
        const int j = j0 + jj;
        // conflict-free lane-indexed LDS.128 (fixed 29-cyc latency, L1-proof)
        const ulonglong2* w1r = (const ulonglong2*)&wtile[jj][0];
        const ulonglong2* per = (const ulonglong2*)&wtile[JT + jj][0];
        ulonglong2 wa = w1r[lane], wb = w1r[32 + lane];
        ulonglong2 pa = per[lane], pb = per[32 + lane];
        u64 w1p0 = wa.x, w1p1 = wa.y, w1p2 = wb.x, w1p3 = wb.y;
        u64 pep0 = pa.x, pep1 = pa.y, pep2 = pb.x, pep3 = pb.y;

        float s[8];
#pragma unroll
        for (int i = 0; i < 8; i++) {
            const u64 nx2 = *(const u64*)&xs2[warp * 8 + i][jj];  // (-xj,-xj)
            u64 a0, a1;
            a0 = fma2_(relu2_(add2_(fma2_(nx2, w1p0, pep0), bp[i][0])), w2p[0], 0ull);
            a1 = fma2_(relu2_(add2_(fma2_(nx2, w1p1, pep1), bp[i][1])), w2p[1], 0ull);
            a0 = fma2_(relu2_(add2_(fma2_(nx2, w1p2, pep2), bp[i][2])), w2p[2], a0);
            a1 = fma2_(relu2_(add2_(fma2_(nx2, w1p3, pep3), bp[i][3])), w2p[3], a1);
            float2 t = unpk(add2_(a0, a1));
            s[i] = t.x + t.y;
        }

        // ---- value-splitting shuffle reduction: 8 vals -> 1 per lane ----
#pragma unroll
        for (int k = 0; k < 4; k++) {
            float snd = h16 ? s[k] : s[k + 4];
            float kp  = h16 ? s[k + 4] : s[k];
            s[k] = kp + __shfl_xor_sync(0xffffffffu, snd, 16);
        }
#pragma unroll
        for (int k = 0; k < 2; k++) {
            float snd = h8 ? s[k] : s[k + 2];
            float kp  = h8 ? s[k + 2] : s[k];
            s[k] = kp + __shfl_xor_sync(0xffffffffu, snd, 8);
        }
        {
            float snd = h4 ? s[0] : s[1];
            float kp  = h4 ? s[1] : s[0];
            s[0] = kp + __shfl_xor_sync(0xffffffffu, snd, 4);
        }
        s[0] += __shfl_xor_sync(0xffffffffu, s[0], 2);
        s[0] += __shfl_xor_sync(0xffffffffu, s[0], 1);

        // lane 4v holds the full sum for n = nb + v
        if ((lane & 3) == 0) {
            const int v = lane >> 2;
            const float nxj = xs2[warp * 8 + v][jj].x;   // = -xj
            out[(nb + v) * (DD + 1) + 1 + j] = -(nxj * (ob2 + s[0]));
        }
    }
}

extern "C" void kernel_launch(void* const* d_in, const int* in_sizes, int n_in,
                              void* d_out, int out_size)
{
    const float* x  = (const float*)d_in[0];
    const float* W1 = (const float*)d_in[1];
    const float* b1 = (const float*)d_in[2];
    const float* W2 = (const float*)d_in[3];
    const float* b2 = (const float*)d_in[4];
    float* out = (float*)d_out;

    // K1: base GEMM + ones column. grid: 64 n-tiles x 4 h-tiles.
    nimo_base_kernel<<<dim3(64, 4), 256>>>(x, W1, b1, out);
    // K2: masked-MLP evaluation. grid: 128 n-tiles x 8 j-tiles of 16.
    nimo_main_kernel<<<dim3(128, 8), 128>>>(x, W1, W2, b2, out);
}